// round 12
// baseline (speedup 1.0000x reference)
#include <cuda_runtime.h>
#include <cuda_bf16.h>
#include <cstdint>

#define DFEAT 128
#define NMAX  50000
#define EMAX  800000
#define BN_EPS 1e-5f
#define SCAN_BLK 256

// -------- scratch (static device globals: no allocation) --------
__device__ float4 g_h[NMAX * 32];           // h = x @ W  (fp32 result)
__device__ float4 g_acc[NMAX * 32];         // gathered output (pre-BN)
__device__ __align__(16) uint2 g_wfh2[4096]; // W hi frags, (bh0,bh1) adjacent
__device__ __align__(16) uint2 g_wfl2[4096]; // W lo frags, (bl0,bl1) adjacent
__device__ float  g_dinv[NMAX];
__device__ __align__(16) int g_ideg[NMAX];
__device__ int    g_indptr[NMAX];
__device__ int    g_cursor[NMAX];
__device__ int    g_srcs[EMAX];
__device__ int    g_bsum[SCAN_BLK];         // published block sums (+1 encoded)
__device__ int    g_barrier;                // grid barrier for scan_fill
__device__ __align__(16) float g_sum[DFEAT];
__device__ __align__(16) float g_sumsq[DFEAT];

__device__ __forceinline__ uint32_t pack_bf2(float a, float b) {
    __nv_bfloat16 ha = __float2bfloat16(a);
    __nv_bfloat16 hb = __float2bfloat16(b);
    return (uint32_t)__bfloat16_as_ushort(ha) |
           ((uint32_t)__bfloat16_as_ushort(hb) << 16);
}

// split float2 -> bf16x2 hi + bf16x2 residual
__device__ __forceinline__ void split2(float2 v, uint32_t& hi, uint32_t& lo) {
    __nv_bfloat162 h = __float22bfloat162_rn(v);
    float2 hb = __bfloat1622float2(h);
    hi = *reinterpret_cast<uint32_t*>(&h);
    lo = pack_bf2(v.x - hb.x, v.y - hb.y);
}

// -------- 1. prep: init scratch + pack W fragments (fused) ----------
// 4096 pairs: p = kt*512 + nt*32 + g*4 + tig, pair = (kh=2kt, kh=2kt+1)
__global__ void prep_kernel(const float* __restrict__ W, int N) {
    int p = blockIdx.x * blockDim.x + threadIdx.x;

    // ---- init section (full grid) ----
    if (p < N) g_ideg[p] = 0;
    if (p < DFEAT) { g_sum[p] = 0.0f; g_sumsq[p] = 0.0f; }
    if (p < SCAN_BLK) g_bsum[p] = 0;
    if (p == 0) g_barrier = 0;

    // ---- W packing section (first 4096 threads) ----
    if (p >= 4096) return;
    int tig = p & 3;
    int g = (p >> 2) & 7;
    int nt = (p >> 5) & 15;
    int kt = p >> 9;
    int n = nt * 8 + g;
    uint2 wh, wl;
    uint32_t* whp = (uint32_t*)&wh;
    uint32_t* wlp = (uint32_t*)&wl;
#pragma unroll
    for (int half = 0; half < 2; half++) {
        int k = (2 * kt + half) * 8 + tig * 2;
        float w0 = W[k * 128 + n];
        float w1 = W[(k + 1) * 128 + n];
        __nv_bfloat16 h0 = __float2bfloat16(w0);
        __nv_bfloat16 h1 = __float2bfloat16(w1);
        whp[half] = (uint32_t)__bfloat16_as_ushort(h0) |
                    ((uint32_t)__bfloat16_as_ushort(h1) << 16);
        wlp[half] = pack_bf2(w0 - __bfloat162float(h0),
                             w1 - __bfloat162float(h1));
    }
    g_wfh2[p] = wh;
    g_wfl2[p] = wl;
}

// -------- 2. FUSED: tensor-core GEMM (blocks < gemm_blocks) + degree ----
__device__ __forceinline__ void mma16816(float* d, uint32_t a0, uint32_t a1,
                                         uint32_t a2, uint32_t a3,
                                         uint32_t b0, uint32_t b1) {
    asm volatile(
        "mma.sync.aligned.m16n8k16.row.col.f32.bf16.bf16.f32 "
        "{%0,%1,%2,%3}, {%4,%5,%6,%7}, {%8,%9}, {%0,%1,%2,%3};"
        : "+f"(d[0]), "+f"(d[1]), "+f"(d[2]), "+f"(d[3])
        : "r"(a0), "r"(a1), "r"(a2), "r"(a3), "r"(b0), "r"(b1));
}

__global__ void __launch_bounds__(256) gemm_degree_kernel(
        const float* __restrict__ x, const int* __restrict__ ei,
        int E, int N, int gemm_blocks) {
    // ---- degree blocks: run in slots left free by the gemm tail ----
    if (blockIdx.x >= gemm_blocks) {
        int base = (blockIdx.x - gemm_blocks) * blockDim.x + threadIdx.x;
        int stride = (gridDim.x - gemm_blocks) * blockDim.x;
        for (int e = base; e < E; e += stride) {
            int col = ei[E + e];
            if ((unsigned)col < (unsigned)N) atomicAdd(&g_ideg[col], 1);
        }
        return;
    }

    // ---- gemm blocks ----
    extern __shared__ uint2 s_w2[];
    uint2* s_wh = s_w2;              // 4096 uint2
    uint2* s_wl = s_w2 + 4096;       // 4096 uint2

    {   // stage 64KB of W fragments
        uint4* dh = (uint4*)s_wh;
        uint4* dl = (uint4*)s_wl;
        const uint4* sh = (const uint4*)g_wfh2;
        const uint4* sl = (const uint4*)g_wfl2;
#pragma unroll
        for (int i = threadIdx.x; i < 2048; i += 256) {
            dh[i] = sh[i];
            dl[i] = sl[i];
        }
    }
    __syncthreads();

    int warp = (blockIdx.x * blockDim.x + threadIdx.x) >> 5;
    int lane = threadIdx.x & 31;
    int g = lane >> 2;
    int tig = lane & 3;
    int m0 = warp * 16;
    if (m0 >= N) return;

    int r0i = m0 + g;       if (r0i > N - 1) r0i = N - 1;
    int r1i = m0 + g + 8;   if (r1i > N - 1) r1i = N - 1;

    float d[16][4];
#pragma unroll
    for (int nt = 0; nt < 16; nt++)
#pragma unroll
        for (int c = 0; c < 4; c++) d[nt][c] = 0.f;

    const float2* x2 = (const float2*)x;
    long long rowA = (long long)r0i * 64;
    long long rowA8 = (long long)r1i * 64;

#pragma unroll
    for (int kt = 0; kt < 8; kt++) {
        int kb = kt * 8 + tig;
        uint32_t ah0, ah1, ah2, ah3, al0, al1, al2, al3;
        split2(x2[rowA + kb], ah0, al0);
        split2(x2[rowA8 + kb], ah1, al1);
        split2(x2[rowA + kb + 4], ah2, al2);
        split2(x2[rowA8 + kb + 4], ah3, al3);
#pragma unroll
        for (int nt = 0; nt < 16; nt++) {
            int p = (kt * 16 + nt) * 32 + lane;
            uint2 bh = s_wh[p];
            uint2 bl = s_wl[p];
            mma16816(d[nt], ah0, ah1, ah2, ah3, bh.x, bh.y);
            mma16816(d[nt], ah0, ah1, ah2, ah3, bl.x, bl.y);
            mma16816(d[nt], al0, al1, al2, al3, bh.x, bh.y);
        }
    }

    float* h = (float*)g_h;
    int r0 = m0 + g;
    int r1 = m0 + g + 8;
#pragma unroll
    for (int nt = 0; nt < 16; nt++) {
        int c = nt * 8 + tig * 2;
        if (r0 < N)
            *(float2*)&h[(long long)r0 * 128 + c] = make_float2(d[nt][0], d[nt][1]);
        if (r1 < N)
            *(float2*)&h[(long long)r1 * 128 + c] = make_float2(d[nt][2], d[nt][3]);
    }
}

// -------- 3. merged scan + fill (single kernel, 196 co-resident blocks) --
// publish block sums (val+1, 0 = unpublished), windowed lookback, grid
// spin-barrier, then grid-stride CSR fill. All blocks provably resident:
// 196 blocks x 256thr, ~2KB smem, low regs -> >= 8 blocks/SM capacity.
__global__ void __launch_bounds__(SCAN_BLK) scan_fill_kernel(
        const int* __restrict__ ei, int E, int N) {
    __shared__ int s[SCAN_BLK];
    __shared__ int red[SCAN_BLK];
    __shared__ int s_off;
    int t = threadIdx.x;
    int b = blockIdx.x;
    int i = b * SCAN_BLK + t;

    int v = (i < N) ? g_ideg[i] : 0;
    s[t] = v;
    __syncthreads();
    // local inclusive scan
    for (int off = 1; off < SCAN_BLK; off <<= 1) {
        int add = (t >= off) ? s[t - off] : 0;
        __syncthreads();
        s[t] += add;
        __syncthreads();
    }
    // publish this block's total (encoded +1 so 0 means unpublished)
    if (t == SCAN_BLK - 1) atomicExch(&g_bsum[b], s[t] + 1);

    // windowed lookback over predecessors
    int part = 0;
    for (int j = t; j < b; j += SCAN_BLK) {
        int val;
        do { val = atomicAdd(&g_bsum[j], 0); } while (val == 0);
        part += val - 1;
    }
    red[t] = part;
    __syncthreads();
    for (int off = SCAN_BLK / 2; off > 0; off >>= 1) {
        if (t < off) red[t] += red[t + off];
        __syncthreads();
    }
    if (t == 0) s_off = red[0];
    __syncthreads();

    if (i < N) {
        int start = s_off + s[t] - v;
        g_indptr[i] = start;
        g_cursor[i] = start;
        g_dinv[i] = rsqrtf((float)(v + 1));   // +1 self loop
    }

    // ---- grid barrier: cursors must be globally visible before fill ----
    __threadfence();
    __syncthreads();
    if (t == 0) {
        atomicAdd(&g_barrier, 1);
        while (atomicAdd(&g_barrier, 0) < gridDim.x) { }
    }
    __syncthreads();
    __threadfence();

    // ---- fill phase: grid-stride over edges ----
    int base = b * SCAN_BLK + t;
    int stride = gridDim.x * SCAN_BLK;
    for (int e = base; e < E; e += stride) {
        int row = ei[e];
        int col = ei[E + e];
        if ((unsigned)row < (unsigned)N && (unsigned)col < (unsigned)N) {
            int pos = atomicAdd(&g_cursor[col], 1);
            if ((unsigned)pos < (unsigned)EMAX) g_srcs[pos] = row;
        }
    }
}

// -------- 4. gather + fused BN stats --------
#define GATHER_BLOCKS 1184
__global__ void __launch_bounds__(256) gather_kernel(
        const float* __restrict__ b, int N) {
    __shared__ float s_sum[DFEAT];
    __shared__ float s_sumsq[DFEAT];
    int tid = threadIdx.x;
    if (tid < DFEAT) { s_sum[tid] = 0.f; s_sumsq[tid] = 0.f; }
    __syncthreads();

    int lane = tid & 31;
    int warp_g = (blockIdx.x * blockDim.x + tid) >> 5;
    int nwarps = (GATHER_BLOCKS * 256) >> 5;

    float4 bb = ((const float4*)b)[lane];

    float ps0 = 0.f, ps1 = 0.f, ps2 = 0.f, ps3 = 0.f;
    float q0 = 0.f, q1 = 0.f, q2 = 0.f, q3 = 0.f;

    for (int w = warp_g; w < N; w += nwarps) {
        float di = g_dinv[w];
        int start = g_indptr[w];
        int cnt = g_ideg[w];

        float4 a = __ldg(&g_h[w * 32 + lane]);
        float selfn = di * di;
        a.x = fmaf(a.x, selfn, bb.x);
        a.y = fmaf(a.y, selfn, bb.y);
        a.z = fmaf(a.z, selfn, bb.z);
        a.w = fmaf(a.w, selfn, bb.w);

        for (int base = 0; base < cnt; base += 32) {
            int j = base + lane;
            int src = 0;
            float nm = 0.f;
            if (j < cnt) {
                src = g_srcs[start + j];
                nm = di * g_dinv[src];
            }
            int m = cnt - base; if (m > 32) m = 32;

            int t = 0;
            for (; t + 4 <= m; t += 4) {
                int r0 = __shfl_sync(0xffffffffu, src, t + 0);
                int r1 = __shfl_sync(0xffffffffu, src, t + 1);
                int r2 = __shfl_sync(0xffffffffu, src, t + 2);
                int r3 = __shfl_sync(0xffffffffu, src, t + 3);
                float n0 = __shfl_sync(0xffffffffu, nm, t + 0);
                float n1 = __shfl_sync(0xffffffffu, nm, t + 1);
                float n2 = __shfl_sync(0xffffffffu, nm, t + 2);
                float n3 = __shfl_sync(0xffffffffu, nm, t + 3);
                float4 v0 = __ldg(&g_h[r0 * 32 + lane]);
                float4 v1 = __ldg(&g_h[r1 * 32 + lane]);
                float4 v2 = __ldg(&g_h[r2 * 32 + lane]);
                float4 v3 = __ldg(&g_h[r3 * 32 + lane]);
                a.x = fmaf(v0.x, n0, a.x); a.y = fmaf(v0.y, n0, a.y);
                a.z = fmaf(v0.z, n0, a.z); a.w = fmaf(v0.w, n0, a.w);
                a.x = fmaf(v1.x, n1, a.x); a.y = fmaf(v1.y, n1, a.y);
                a.z = fmaf(v1.z, n1, a.z); a.w = fmaf(v1.w, n1, a.w);
                a.x = fmaf(v2.x, n2, a.x); a.y = fmaf(v2.y, n2, a.y);
                a.z = fmaf(v2.z, n2, a.z); a.w = fmaf(v2.w, n2, a.w);
                a.x = fmaf(v3.x, n3, a.x); a.y = fmaf(v3.y, n3, a.y);
                a.z = fmaf(v3.z, n3, a.z); a.w = fmaf(v3.w, n3, a.w);
            }
            for (; t < m; t++) {
                int r = __shfl_sync(0xffffffffu, src, t);
                float nn = __shfl_sync(0xffffffffu, nm, t);
                float4 v = __ldg(&g_h[r * 32 + lane]);
                a.x = fmaf(v.x, nn, a.x); a.y = fmaf(v.y, nn, a.y);
                a.z = fmaf(v.z, nn, a.z); a.w = fmaf(v.w, nn, a.w);
            }
        }

        g_acc[w * 32 + lane] = a;

        ps0 += a.x; ps1 += a.y; ps2 += a.z; ps3 += a.w;
        q0 = fmaf(a.x, a.x, q0); q1 = fmaf(a.y, a.y, q1);
        q2 = fmaf(a.z, a.z, q2); q3 = fmaf(a.w, a.w, q3);
    }

    int c = lane * 4;
    atomicAdd(&s_sum[c + 0], ps0);
    atomicAdd(&s_sum[c + 1], ps1);
    atomicAdd(&s_sum[c + 2], ps2);
    atomicAdd(&s_sum[c + 3], ps3);
    atomicAdd(&s_sumsq[c + 0], q0);
    atomicAdd(&s_sumsq[c + 1], q1);
    atomicAdd(&s_sumsq[c + 2], q2);
    atomicAdd(&s_sumsq[c + 3], q3);
    __syncthreads();

    if (tid < DFEAT) {
        atomicAdd(&g_sum[tid], s_sum[tid]);
        atomicAdd(&g_sumsq[tid], s_sumsq[tid]);
    }
}

// -------- 5. BN normalize + relu + residual --------
__global__ void finalize_kernel(const float* __restrict__ x,
                                const float* __restrict__ gamma,
                                const float* __restrict__ beta,
                                float* __restrict__ out, int N) {
    int i = blockIdx.x * blockDim.x + threadIdx.x;
    int total = N * 32;
    if (i >= total) return;
    int d4 = i & 31;
    float inv_n = 1.0f / (float)N;

    float4 a  = g_acc[i];
    float4 xv = ((const float4*)x)[i];
    float4 g  = ((const float4*)gamma)[d4];
    float4 bt = ((const float4*)beta)[d4];
    float4 sm = ((const float4*)g_sum)[d4];
    float4 sq = ((const float4*)g_sumsq)[d4];

    float4 o;
    {
        float m = sm.x * inv_n;
        float var = sq.x * inv_n - m * m;
        float v = (a.x - m) * rsqrtf(var + BN_EPS) * g.x + bt.x;
        o.x = fmaxf(v, 0.f) + xv.x;
    }
    {
        float m = sm.y * inv_n;
        float var = sq.y * inv_n - m * m;
        float v = (a.y - m) * rsqrtf(var + BN_EPS) * g.y + bt.y;
        o.y = fmaxf(v, 0.f) + xv.y;
    }
    {
        float m = sm.z * inv_n;
        float var = sq.z * inv_n - m * m;
        float v = (a.z - m) * rsqrtf(var + BN_EPS) * g.z + bt.z;
        o.z = fmaxf(v, 0.f) + xv.z;
    }
    {
        float m = sm.w * inv_n;
        float var = sq.w * inv_n - m * m;
        float v = (a.w - m) * rsqrtf(var + BN_EPS) * g.w + bt.w;
        o.w = fmaxf(v, 0.f) + xv.w;
    }
    ((float4*)out)[i] = o;
}

extern "C" void kernel_launch(void* const* d_in, const int* in_sizes, int n_in,
                              void* d_out, int out_size) {
    const float* x     = (const float*)d_in[0];
    const int*   ei    = (const int*)d_in[1];
    const float* W     = (const float*)d_in[2];
    const float* b     = (const float*)d_in[3];
    const float* gamma = (const float*)d_in[4];
    const float* beta  = (const float*)d_in[5];
    float*       out   = (float*)d_out;

    int N = in_sizes[0] / DFEAT;
    int E = in_sizes[1] / 2;
    if (E > EMAX) E = EMAX;
    int NB = (N + SCAN_BLK - 1) / SCAN_BLK;   // 196 (<= 256)

    int nstrips = (N + 15) / 16;
    int gemm_blocks = (nstrips + 7) / 8;   // 391
    int deg_blocks = 512;                  // appended; hidden in gemm tail
    const int GEMM_SMEM = 65536;

    cudaFuncSetAttribute(gemm_degree_kernel,
                         cudaFuncAttributeMaxDynamicSharedMemorySize, GEMM_SMEM);

    prep_kernel<<<NB, SCAN_BLK>>>(W, N);                                 // 1
    gemm_degree_kernel<<<gemm_blocks + deg_blocks, 256, GEMM_SMEM>>>(
        x, ei, E, N, gemm_blocks);                                       // 2
    scan_fill_kernel<<<NB, SCAN_BLK>>>(ei, E, N);                        // 3
    gather_kernel<<<GATHER_BLOCKS, 256>>>(b, N);                         // 4
    finalize_kernel<<<(N * 32 + 255) / 256, 256>>>(x, gamma, beta, out, N); // 5
}

// round 13
// speedup vs baseline: 1.0315x; 1.0315x over previous
#include <cuda_runtime.h>
#include <cuda_bf16.h>
#include <cstdint>

#define DFEAT 128
#define NMAX  50000
#define EMAX  800000
#define BN_EPS 1e-5f
#define SCAN_BLK 256

// -------- scratch (static device globals: no allocation) --------
__device__ float4 g_h[NMAX * 32];           // h = x @ W  (fp32 result)
__device__ float4 g_acc[NMAX * 32];         // gathered output (pre-BN)
__device__ __align__(16) uint2 g_wfh2[4096]; // W hi frags, (bh0,bh1) adjacent
__device__ __align__(16) uint2 g_wfl2[4096]; // W lo frags, (bl0,bl1) adjacent
__device__ float  g_dinv[NMAX];
__device__ __align__(16) int g_ideg[NMAX];
__device__ int    g_indptr[NMAX];
__device__ int    g_cursor[NMAX];
__device__ int    g_srcs[EMAX];
__device__ int    g_bsum[SCAN_BLK];
__device__ __align__(16) float g_sum[DFEAT];
__device__ __align__(16) float g_sumsq[DFEAT];

__device__ __forceinline__ uint32_t pack_bf2(float a, float b) {
    __nv_bfloat16 ha = __float2bfloat16(a);
    __nv_bfloat16 hb = __float2bfloat16(b);
    return (uint32_t)__bfloat16_as_ushort(ha) |
           ((uint32_t)__bfloat16_as_ushort(hb) << 16);
}

// split float2 -> bf16x2 hi + bf16x2 residual
__device__ __forceinline__ void split2(float2 v, uint32_t& hi, uint32_t& lo) {
    __nv_bfloat162 h = __float22bfloat162_rn(v);
    float2 hb = __bfloat1622float2(h);
    hi = *reinterpret_cast<uint32_t*>(&h);
    lo = pack_bf2(v.x - hb.x, v.y - hb.y);
}

// -------- 1. prep: init scratch + pack W fragments (fused; all work
// per-thread independent -> no parallelism lost) --------------------
// 4096 pairs: p = kt*512 + nt*32 + g*4 + tig, pair = (kh=2kt, kh=2kt+1)
__global__ void prep_kernel(const float* __restrict__ W, int N) {
    int p = blockIdx.x * blockDim.x + threadIdx.x;

    if (p < N) g_ideg[p] = 0;
    if (p < DFEAT) { g_sum[p] = 0.0f; g_sumsq[p] = 0.0f; }

    if (p >= 4096) return;
    int tig = p & 3;
    int g = (p >> 2) & 7;
    int nt = (p >> 5) & 15;
    int kt = p >> 9;
    int n = nt * 8 + g;
    uint2 wh, wl;
    uint32_t* whp = (uint32_t*)&wh;
    uint32_t* wlp = (uint32_t*)&wl;
#pragma unroll
    for (int half = 0; half < 2; half++) {
        int k = (2 * kt + half) * 8 + tig * 2;
        float w0 = W[k * 128 + n];
        float w1 = W[(k + 1) * 128 + n];
        __nv_bfloat16 h0 = __float2bfloat16(w0);
        __nv_bfloat16 h1 = __float2bfloat16(w1);
        whp[half] = (uint32_t)__bfloat16_as_ushort(h0) |
                    ((uint32_t)__bfloat16_as_ushort(h1) << 16);
        wlp[half] = pack_bf2(w0 - __bfloat162float(h0),
                             w1 - __bfloat162float(h1));
    }
    g_wfh2[p] = wh;
    g_wfl2[p] = wl;
}

// -------- 2. FUSED: tensor-core GEMM (blocks < gemm_blocks) + degree ----
__device__ __forceinline__ void mma16816(float* d, uint32_t a0, uint32_t a1,
                                         uint32_t a2, uint32_t a3,
                                         uint32_t b0, uint32_t b1) {
    asm volatile(
        "mma.sync.aligned.m16n8k16.row.col.f32.bf16.bf16.f32 "
        "{%0,%1,%2,%3}, {%4,%5,%6,%7}, {%8,%9}, {%0,%1,%2,%3};"
        : "+f"(d[0]), "+f"(d[1]), "+f"(d[2]), "+f"(d[3])
        : "r"(a0), "r"(a1), "r"(a2), "r"(a3), "r"(b0), "r"(b1));
}

__global__ void __launch_bounds__(256) gemm_degree_kernel(
        const float* __restrict__ x, const int* __restrict__ ei,
        int E, int N, int gemm_blocks) {
    // ---- degree blocks: run in slots left free by the gemm tail ----
    if (blockIdx.x >= gemm_blocks) {
        int base = (blockIdx.x - gemm_blocks) * blockDim.x + threadIdx.x;
        int stride = (gridDim.x - gemm_blocks) * blockDim.x;
        for (int e = base; e < E; e += stride) {
            int col = ei[E + e];
            if ((unsigned)col < (unsigned)N) atomicAdd(&g_ideg[col], 1);
        }
        return;
    }

    // ---- gemm blocks ----
    extern __shared__ uint2 s_w2[];
    uint2* s_wh = s_w2;              // 4096 uint2
    uint2* s_wl = s_w2 + 4096;       // 4096 uint2

    {   // stage 64KB of W fragments
        uint4* dh = (uint4*)s_wh;
        uint4* dl = (uint4*)s_wl;
        const uint4* sh = (const uint4*)g_wfh2;
        const uint4* sl = (const uint4*)g_wfl2;
#pragma unroll
        for (int i = threadIdx.x; i < 2048; i += 256) {
            dh[i] = sh[i];
            dl[i] = sl[i];
        }
    }
    __syncthreads();

    int warp = (blockIdx.x * blockDim.x + threadIdx.x) >> 5;
    int lane = threadIdx.x & 31;
    int g = lane >> 2;
    int tig = lane & 3;
    int m0 = warp * 16;
    if (m0 >= N) return;

    int r0i = m0 + g;       if (r0i > N - 1) r0i = N - 1;
    int r1i = m0 + g + 8;   if (r1i > N - 1) r1i = N - 1;

    float d[16][4];
#pragma unroll
    for (int nt = 0; nt < 16; nt++)
#pragma unroll
        for (int c = 0; c < 4; c++) d[nt][c] = 0.f;

    const float2* x2 = (const float2*)x;
    long long rowA = (long long)r0i * 64;
    long long rowA8 = (long long)r1i * 64;

#pragma unroll
    for (int kt = 0; kt < 8; kt++) {
        int kb = kt * 8 + tig;
        uint32_t ah0, ah1, ah2, ah3, al0, al1, al2, al3;
        split2(x2[rowA + kb], ah0, al0);
        split2(x2[rowA8 + kb], ah1, al1);
        split2(x2[rowA + kb + 4], ah2, al2);
        split2(x2[rowA8 + kb + 4], ah3, al3);
#pragma unroll
        for (int nt = 0; nt < 16; nt++) {
            int p = (kt * 16 + nt) * 32 + lane;
            uint2 bh = s_wh[p];
            uint2 bl = s_wl[p];
            mma16816(d[nt], ah0, ah1, ah2, ah3, bh.x, bh.y);
            mma16816(d[nt], ah0, ah1, ah2, ah3, bl.x, bl.y);
            mma16816(d[nt], al0, al1, al2, al3, bh.x, bh.y);
        }
    }

    float* h = (float*)g_h;
    int r0 = m0 + g;
    int r1 = m0 + g + 8;
#pragma unroll
    for (int nt = 0; nt < 16; nt++) {
        int c = nt * 8 + tig * 2;
        if (r0 < N)
            *(float2*)&h[(long long)r0 * 128 + c] = make_float2(d[nt][0], d[nt][1]);
        if (r1 < N)
            *(float2*)&h[(long long)r1 * 128 + c] = make_float2(d[nt][2], d[nt][3]);
    }
}

// -------- 3a. per-block degree sums --------
__global__ void scan_blocksum_kernel(int N) {
    __shared__ int s[SCAN_BLK];
    int i = blockIdx.x * SCAN_BLK + threadIdx.x;
    s[threadIdx.x] = (i < N) ? g_ideg[i] : 0;
    __syncthreads();
    for (int off = SCAN_BLK / 2; off > 0; off >>= 1) {
        if (threadIdx.x < off) s[threadIdx.x] += s[threadIdx.x + off];
        __syncthreads();
    }
    if (threadIdx.x == 0) g_bsum[blockIdx.x] = s[0];
}

// -------- 3b. scan_final: offset via reduce of g_bsum[0..blockIdx) --
__global__ void scan_final_kernel(int N) {
    __shared__ int s[SCAN_BLK];
    __shared__ int red[SCAN_BLK];
    __shared__ int s_off;
    int t = threadIdx.x;

    int part = 0;
    for (int j = t; j < blockIdx.x; j += SCAN_BLK) part += g_bsum[j];
    red[t] = part;
    __syncthreads();
    for (int off = SCAN_BLK / 2; off > 0; off >>= 1) {
        if (t < off) red[t] += red[t + off];
        __syncthreads();
    }
    if (t == 0) s_off = red[0];
    __syncthreads();

    int i = blockIdx.x * SCAN_BLK + t;
    int v = (i < N) ? g_ideg[i] : 0;
    s[t] = v;
    __syncthreads();
    for (int off = 1; off < SCAN_BLK; off <<= 1) {
        int add = (t >= off) ? s[t - off] : 0;
        __syncthreads();
        s[t] += add;
        __syncthreads();
    }
    if (i < N) {
        int start = s_off + s[t] - v;
        g_indptr[i] = start;
        g_cursor[i] = start;
        g_dinv[i] = rsqrtf((float)(v + 1));
    }
}

// -------- 4. CSR fill (full-grid parallelism) --------
__global__ void fill_kernel(const int* __restrict__ ei, int E, int N) {
    int e = blockIdx.x * blockDim.x + threadIdx.x;
    if (e < E) {
        int row = ei[e];
        int col = ei[E + e];
        if ((unsigned)row < (unsigned)N && (unsigned)col < (unsigned)N) {
            int pos = atomicAdd(&g_cursor[col], 1);
            if ((unsigned)pos < (unsigned)EMAX) g_srcs[pos] = row;
        }
    }
}

// -------- 5. gather + fused BN stats --------
#define GATHER_BLOCKS 1184
__global__ void __launch_bounds__(256) gather_kernel(
        const float* __restrict__ b, int N) {
    __shared__ float s_sum[DFEAT];
    __shared__ float s_sumsq[DFEAT];
    int tid = threadIdx.x;
    if (tid < DFEAT) { s_sum[tid] = 0.f; s_sumsq[tid] = 0.f; }
    __syncthreads();

    int lane = tid & 31;
    int warp_g = (blockIdx.x * blockDim.x + tid) >> 5;
    int nwarps = (GATHER_BLOCKS * 256) >> 5;

    float4 bb = ((const float4*)b)[lane];

    float ps0 = 0.f, ps1 = 0.f, ps2 = 0.f, ps3 = 0.f;
    float q0 = 0.f, q1 = 0.f, q2 = 0.f, q3 = 0.f;

    for (int w = warp_g; w < N; w += nwarps) {
        float di = g_dinv[w];
        int start = g_indptr[w];
        int cnt = g_ideg[w];

        float4 a = __ldg(&g_h[w * 32 + lane]);
        float selfn = di * di;
        a.x = fmaf(a.x, selfn, bb.x);
        a.y = fmaf(a.y, selfn, bb.y);
        a.z = fmaf(a.z, selfn, bb.z);
        a.w = fmaf(a.w, selfn, bb.w);

        for (int base = 0; base < cnt; base += 32) {
            int j = base + lane;
            int src = 0;
            float nm = 0.f;
            if (j < cnt) {
                src = g_srcs[start + j];
                nm = di * g_dinv[src];
            }
            int m = cnt - base; if (m > 32) m = 32;

            int t = 0;
            for (; t + 4 <= m; t += 4) {
                int r0 = __shfl_sync(0xffffffffu, src, t + 0);
                int r1 = __shfl_sync(0xffffffffu, src, t + 1);
                int r2 = __shfl_sync(0xffffffffu, src, t + 2);
                int r3 = __shfl_sync(0xffffffffu, src, t + 3);
                float n0 = __shfl_sync(0xffffffffu, nm, t + 0);
                float n1 = __shfl_sync(0xffffffffu, nm, t + 1);
                float n2 = __shfl_sync(0xffffffffu, nm, t + 2);
                float n3 = __shfl_sync(0xffffffffu, nm, t + 3);
                float4 v0 = __ldg(&g_h[r0 * 32 + lane]);
                float4 v1 = __ldg(&g_h[r1 * 32 + lane]);
                float4 v2 = __ldg(&g_h[r2 * 32 + lane]);
                float4 v3 = __ldg(&g_h[r3 * 32 + lane]);
                a.x = fmaf(v0.x, n0, a.x); a.y = fmaf(v0.y, n0, a.y);
                a.z = fmaf(v0.z, n0, a.z); a.w = fmaf(v0.w, n0, a.w);
                a.x = fmaf(v1.x, n1, a.x); a.y = fmaf(v1.y, n1, a.y);
                a.z = fmaf(v1.z, n1, a.z); a.w = fmaf(v1.w, n1, a.w);
                a.x = fmaf(v2.x, n2, a.x); a.y = fmaf(v2.y, n2, a.y);
                a.z = fmaf(v2.z, n2, a.z); a.w = fmaf(v2.w, n2, a.w);
                a.x = fmaf(v3.x, n3, a.x); a.y = fmaf(v3.y, n3, a.y);
                a.z = fmaf(v3.z, n3, a.z); a.w = fmaf(v3.w, n3, a.w);
            }
            for (; t < m; t++) {
                int r = __shfl_sync(0xffffffffu, src, t);
                float nn = __shfl_sync(0xffffffffu, nm, t);
                float4 v = __ldg(&g_h[r * 32 + lane]);
                a.x = fmaf(v.x, nn, a.x); a.y = fmaf(v.y, nn, a.y);
                a.z = fmaf(v.z, nn, a.z); a.w = fmaf(v.w, nn, a.w);
            }
        }

        g_acc[w * 32 + lane] = a;

        ps0 += a.x; ps1 += a.y; ps2 += a.z; ps3 += a.w;
        q0 = fmaf(a.x, a.x, q0); q1 = fmaf(a.y, a.y, q1);
        q2 = fmaf(a.z, a.z, q2); q3 = fmaf(a.w, a.w, q3);
    }

    int c = lane * 4;
    atomicAdd(&s_sum[c + 0], ps0);
    atomicAdd(&s_sum[c + 1], ps1);
    atomicAdd(&s_sum[c + 2], ps2);
    atomicAdd(&s_sum[c + 3], ps3);
    atomicAdd(&s_sumsq[c + 0], q0);
    atomicAdd(&s_sumsq[c + 1], q1);
    atomicAdd(&s_sumsq[c + 2], q2);
    atomicAdd(&s_sumsq[c + 3], q3);
    __syncthreads();

    if (tid < DFEAT) {
        atomicAdd(&g_sum[tid], s_sum[tid]);
        atomicAdd(&g_sumsq[tid], s_sumsq[tid]);
    }
}

// -------- 6. BN normalize + relu + residual --------
__global__ void finalize_kernel(const float* __restrict__ x,
                                const float* __restrict__ gamma,
                                const float* __restrict__ beta,
                                float* __restrict__ out, int N) {
    int i = blockIdx.x * blockDim.x + threadIdx.x;
    int total = N * 32;
    if (i >= total) return;
    int d4 = i & 31;
    float inv_n = 1.0f / (float)N;

    float4 a  = g_acc[i];
    float4 xv = ((const float4*)x)[i];
    float4 g  = ((const float4*)gamma)[d4];
    float4 bt = ((const float4*)beta)[d4];
    float4 sm = ((const float4*)g_sum)[d4];
    float4 sq = ((const float4*)g_sumsq)[d4];

    float4 o;
    {
        float m = sm.x * inv_n;
        float var = sq.x * inv_n - m * m;
        float v = (a.x - m) * rsqrtf(var + BN_EPS) * g.x + bt.x;
        o.x = fmaxf(v, 0.f) + xv.x;
    }
    {
        float m = sm.y * inv_n;
        float var = sq.y * inv_n - m * m;
        float v = (a.y - m) * rsqrtf(var + BN_EPS) * g.y + bt.y;
        o.y = fmaxf(v, 0.f) + xv.y;
    }
    {
        float m = sm.z * inv_n;
        float var = sq.z * inv_n - m * m;
        float v = (a.z - m) * rsqrtf(var + BN_EPS) * g.z + bt.z;
        o.z = fmaxf(v, 0.f) + xv.z;
    }
    {
        float m = sm.w * inv_n;
        float var = sq.w * inv_n - m * m;
        float v = (a.w - m) * rsqrtf(var + BN_EPS) * g.w + bt.w;
        o.w = fmaxf(v, 0.f) + xv.w;
    }
    ((float4*)out)[i] = o;
}

extern "C" void kernel_launch(void* const* d_in, const int* in_sizes, int n_in,
                              void* d_out, int out_size) {
    const float* x     = (const float*)d_in[0];
    const int*   ei    = (const int*)d_in[1];
    const float* W     = (const float*)d_in[2];
    const float* b     = (const float*)d_in[3];
    const float* gamma = (const float*)d_in[4];
    const float* beta  = (const float*)d_in[5];
    float*       out   = (float*)d_out;

    int N = in_sizes[0] / DFEAT;
    int E = in_sizes[1] / 2;
    if (E > EMAX) E = EMAX;
    int NB = (N + SCAN_BLK - 1) / SCAN_BLK;   // 196 (<= 256)

    int nstrips = (N + 15) / 16;
    int gemm_blocks = (nstrips + 7) / 8;   // 391
    int deg_blocks = 512;                  // appended; hidden in gemm tail
    const int GEMM_SMEM = 65536;

    cudaFuncSetAttribute(gemm_degree_kernel,
                         cudaFuncAttributeMaxDynamicSharedMemorySize, GEMM_SMEM);

    prep_kernel<<<NB, SCAN_BLK>>>(W, N);                                 // 1
    gemm_degree_kernel<<<gemm_blocks + deg_blocks, 256, GEMM_SMEM>>>(
        x, ei, E, N, gemm_blocks);                                       // 2
    scan_blocksum_kernel<<<NB, SCAN_BLK>>>(N);                           // 3
    scan_final_kernel<<<NB, SCAN_BLK>>>(N);                              // 4
    fill_kernel<<<(E + 255) / 256, 256>>>(ei, E, N);                     // 5
    gather_kernel<<<GATHER_BLOCKS, 256>>>(b, N);                         // 6
    finalize_kernel<<<(N * 32 + 255) / 256, 256>>>(x, gamma, beta, out, N); // 7
}

// round 14
// speedup vs baseline: 1.0859x; 1.0527x over previous
#include <cuda_runtime.h>
#include <cuda_bf16.h>
#include <cstdint>

#define DFEAT 128
#define NMAX  50000
#define EMAX  800000
#define BN_EPS 1e-5f
#define SCAN_BLK 256

// -------- scratch (static device globals: no allocation) --------
__device__ float4 g_h[NMAX * 32];           // h = x @ W  (fp32 result)
__device__ float4 g_acc[NMAX * 32];         // gathered output (pre-BN)
__device__ __align__(16) uint2 g_wfh2[4096]; // W hi frags, (bh0,bh1) adjacent
__device__ __align__(16) uint2 g_wfl2[4096]; // W lo frags, (bl0,bl1) adjacent
__device__ float  g_dinv[NMAX];
__device__ __align__(16) int g_ideg[NMAX];
__device__ int    g_indptr[NMAX];
__device__ int    g_cursor[NMAX];
__device__ int    g_srcs[EMAX];
__device__ int    g_bsum[SCAN_BLK];
__device__ __align__(16) float g_sum[DFEAT];
__device__ __align__(16) float g_sumsq[DFEAT];

__device__ __forceinline__ uint32_t pack_bf2(float a, float b) {
    __nv_bfloat16 ha = __float2bfloat16(a);
    __nv_bfloat16 hb = __float2bfloat16(b);
    return (uint32_t)__bfloat16_as_ushort(ha) |
           ((uint32_t)__bfloat16_as_ushort(hb) << 16);
}

// split float2 -> bf16x2 hi + bf16x2 residual
__device__ __forceinline__ void split2(float2 v, uint32_t& hi, uint32_t& lo) {
    __nv_bfloat162 h = __float22bfloat162_rn(v);
    float2 hb = __bfloat1622float2(h);
    hi = *reinterpret_cast<uint32_t*>(&h);
    lo = pack_bf2(v.x - hb.x, v.y - hb.y);
}

// -------- 1. prep: init scratch + pack W fragments (fused) ----------
__global__ void prep_kernel(const float* __restrict__ W, int N) {
    int p = blockIdx.x * blockDim.x + threadIdx.x;

    if (p < N) g_ideg[p] = 0;
    if (p < DFEAT) { g_sum[p] = 0.0f; g_sumsq[p] = 0.0f; }

    if (p >= 4096) return;
    int tig = p & 3;
    int g = (p >> 2) & 7;
    int nt = (p >> 5) & 15;
    int kt = p >> 9;
    int n = nt * 8 + g;
    uint2 wh, wl;
    uint32_t* whp = (uint32_t*)&wh;
    uint32_t* wlp = (uint32_t*)&wl;
#pragma unroll
    for (int half = 0; half < 2; half++) {
        int k = (2 * kt + half) * 8 + tig * 2;
        float w0 = W[k * 128 + n];
        float w1 = W[(k + 1) * 128 + n];
        __nv_bfloat16 h0 = __float2bfloat16(w0);
        __nv_bfloat16 h1 = __float2bfloat16(w1);
        whp[half] = (uint32_t)__bfloat16_as_ushort(h0) |
                    ((uint32_t)__bfloat16_as_ushort(h1) << 16);
        wlp[half] = pack_bf2(w0 - __bfloat162float(h0),
                             w1 - __bfloat162float(h1));
    }
    g_wfh2[p] = wh;
    g_wfl2[p] = wl;
}

// -------- 2A. tensor-core GEMM (stream 0) --------
__device__ __forceinline__ void mma16816(float* d, uint32_t a0, uint32_t a1,
                                         uint32_t a2, uint32_t a3,
                                         uint32_t b0, uint32_t b1) {
    asm volatile(
        "mma.sync.aligned.m16n8k16.row.col.f32.bf16.bf16.f32 "
        "{%0,%1,%2,%3}, {%4,%5,%6,%7}, {%8,%9}, {%0,%1,%2,%3};"
        : "+f"(d[0]), "+f"(d[1]), "+f"(d[2]), "+f"(d[3])
        : "r"(a0), "r"(a1), "r"(a2), "r"(a3), "r"(b0), "r"(b1));
}

__global__ void __launch_bounds__(256) gemm_mma_kernel(
        const float* __restrict__ x, int N) {
    extern __shared__ uint2 s_w2[];
    uint2* s_wh = s_w2;              // 4096 uint2
    uint2* s_wl = s_w2 + 4096;       // 4096 uint2

    {   // stage 64KB of W fragments
        uint4* dh = (uint4*)s_wh;
        uint4* dl = (uint4*)s_wl;
        const uint4* sh = (const uint4*)g_wfh2;
        const uint4* sl = (const uint4*)g_wfl2;
#pragma unroll
        for (int i = threadIdx.x; i < 2048; i += 256) {
            dh[i] = sh[i];
            dl[i] = sl[i];
        }
    }
    __syncthreads();

    int warp = (blockIdx.x * blockDim.x + threadIdx.x) >> 5;
    int lane = threadIdx.x & 31;
    int g = lane >> 2;
    int tig = lane & 3;
    int m0 = warp * 16;
    if (m0 >= N) return;

    int r0i = m0 + g;       if (r0i > N - 1) r0i = N - 1;
    int r1i = m0 + g + 8;   if (r1i > N - 1) r1i = N - 1;

    float d[16][4];
#pragma unroll
    for (int nt = 0; nt < 16; nt++)
#pragma unroll
        for (int c = 0; c < 4; c++) d[nt][c] = 0.f;

    const float2* x2 = (const float2*)x;
    long long rowA = (long long)r0i * 64;
    long long rowA8 = (long long)r1i * 64;

#pragma unroll
    for (int kt = 0; kt < 8; kt++) {
        int kb = kt * 8 + tig;
        uint32_t ah0, ah1, ah2, ah3, al0, al1, al2, al3;
        split2(x2[rowA + kb], ah0, al0);
        split2(x2[rowA8 + kb], ah1, al1);
        split2(x2[rowA + kb + 4], ah2, al2);
        split2(x2[rowA8 + kb + 4], ah3, al3);
#pragma unroll
        for (int nt = 0; nt < 16; nt++) {
            int p = (kt * 16 + nt) * 32 + lane;
            uint2 bh = s_wh[p];
            uint2 bl = s_wl[p];
            mma16816(d[nt], ah0, ah1, ah2, ah3, bh.x, bh.y);
            mma16816(d[nt], ah0, ah1, ah2, ah3, bl.x, bl.y);
            mma16816(d[nt], al0, al1, al2, al3, bh.x, bh.y);
        }
    }

    float* h = (float*)g_h;
    int r0 = m0 + g;
    int r1 = m0 + g + 8;
#pragma unroll
    for (int nt = 0; nt < 16; nt++) {
        int c = nt * 8 + tig * 2;
        if (r0 < N)
            *(float2*)&h[(long long)r0 * 128 + c] = make_float2(d[nt][0], d[nt][1]);
        if (r1 < N)
            *(float2*)&h[(long long)r1 * 128 + c] = make_float2(d[nt][2], d[nt][3]);
    }
}

// -------- 2B. degree (side stream) --------
__global__ void degree_kernel(const int* __restrict__ ei, int E, int N) {
    int e = blockIdx.x * blockDim.x + threadIdx.x;
    if (e < E) {
        int col = ei[E + e];
        if ((unsigned)col < (unsigned)N) atomicAdd(&g_ideg[col], 1);
    }
}

// -------- 3a. per-block degree sums (side stream) --------
__global__ void scan_blocksum_kernel(int N) {
    __shared__ int s[SCAN_BLK];
    int i = blockIdx.x * SCAN_BLK + threadIdx.x;
    s[threadIdx.x] = (i < N) ? g_ideg[i] : 0;
    __syncthreads();
    for (int off = SCAN_BLK / 2; off > 0; off >>= 1) {
        if (threadIdx.x < off) s[threadIdx.x] += s[threadIdx.x + off];
        __syncthreads();
    }
    if (threadIdx.x == 0) g_bsum[blockIdx.x] = s[0];
}

// -------- 3b. scan_final (side stream) --------
__global__ void scan_final_kernel(int N) {
    __shared__ int s[SCAN_BLK];
    __shared__ int red[SCAN_BLK];
    __shared__ int s_off;
    int t = threadIdx.x;

    int part = 0;
    for (int j = t; j < blockIdx.x; j += SCAN_BLK) part += g_bsum[j];
    red[t] = part;
    __syncthreads();
    for (int off = SCAN_BLK / 2; off > 0; off >>= 1) {
        if (t < off) red[t] += red[t + off];
        __syncthreads();
    }
    if (t == 0) s_off = red[0];
    __syncthreads();

    int i = blockIdx.x * SCAN_BLK + t;
    int v = (i < N) ? g_ideg[i] : 0;
    s[t] = v;
    __syncthreads();
    for (int off = 1; off < SCAN_BLK; off <<= 1) {
        int add = (t >= off) ? s[t - off] : 0;
        __syncthreads();
        s[t] += add;
        __syncthreads();
    }
    if (i < N) {
        int start = s_off + s[t] - v;
        g_indptr[i] = start;
        g_cursor[i] = start;
        g_dinv[i] = rsqrtf((float)(v + 1));
    }
}

// -------- 4. CSR fill (side stream, full-grid parallelism) --------
__global__ void fill_kernel(const int* __restrict__ ei, int E, int N) {
    int e = blockIdx.x * blockDim.x + threadIdx.x;
    if (e < E) {
        int row = ei[e];
        int col = ei[E + e];
        if ((unsigned)row < (unsigned)N && (unsigned)col < (unsigned)N) {
            int pos = atomicAdd(&g_cursor[col], 1);
            if ((unsigned)pos < (unsigned)EMAX) g_srcs[pos] = row;
        }
    }
}

// -------- 5. gather + fused BN stats --------
#define GATHER_BLOCKS 1184
__global__ void __launch_bounds__(256) gather_kernel(
        const float* __restrict__ b, int N) {
    __shared__ float s_sum[DFEAT];
    __shared__ float s_sumsq[DFEAT];
    int tid = threadIdx.x;
    if (tid < DFEAT) { s_sum[tid] = 0.f; s_sumsq[tid] = 0.f; }
    __syncthreads();

    int lane = tid & 31;
    int warp_g = (blockIdx.x * blockDim.x + tid) >> 5;
    int nwarps = (GATHER_BLOCKS * 256) >> 5;

    float4 bb = ((const float4*)b)[lane];

    float ps0 = 0.f, ps1 = 0.f, ps2 = 0.f, ps3 = 0.f;
    float q0 = 0.f, q1 = 0.f, q2 = 0.f, q3 = 0.f;

    for (int w = warp_g; w < N; w += nwarps) {
        float di = g_dinv[w];
        int start = g_indptr[w];
        int cnt = g_ideg[w];

        float4 a = __ldg(&g_h[w * 32 + lane]);
        float selfn = di * di;
        a.x = fmaf(a.x, selfn, bb.x);
        a.y = fmaf(a.y, selfn, bb.y);
        a.z = fmaf(a.z, selfn, bb.z);
        a.w = fmaf(a.w, selfn, bb.w);

        for (int base = 0; base < cnt; base += 32) {
            int j = base + lane;
            int src = 0;
            float nm = 0.f;
            if (j < cnt) {
                src = g_srcs[start + j];
                nm = di * g_dinv[src];
            }
            int m = cnt - base; if (m > 32) m = 32;

            int t = 0;
            for (; t + 4 <= m; t += 4) {
                int r0 = __shfl_sync(0xffffffffu, src, t + 0);
                int r1 = __shfl_sync(0xffffffffu, src, t + 1);
                int r2 = __shfl_sync(0xffffffffu, src, t + 2);
                int r3 = __shfl_sync(0xffffffffu, src, t + 3);
                float n0 = __shfl_sync(0xffffffffu, nm, t + 0);
                float n1 = __shfl_sync(0xffffffffu, nm, t + 1);
                float n2 = __shfl_sync(0xffffffffu, nm, t + 2);
                float n3 = __shfl_sync(0xffffffffu, nm, t + 3);
                float4 v0 = __ldg(&g_h[r0 * 32 + lane]);
                float4 v1 = __ldg(&g_h[r1 * 32 + lane]);
                float4 v2 = __ldg(&g_h[r2 * 32 + lane]);
                float4 v3 = __ldg(&g_h[r3 * 32 + lane]);
                a.x = fmaf(v0.x, n0, a.x); a.y = fmaf(v0.y, n0, a.y);
                a.z = fmaf(v0.z, n0, a.z); a.w = fmaf(v0.w, n0, a.w);
                a.x = fmaf(v1.x, n1, a.x); a.y = fmaf(v1.y, n1, a.y);
                a.z = fmaf(v1.z, n1, a.z); a.w = fmaf(v1.w, n1, a.w);
                a.x = fmaf(v2.x, n2, a.x); a.y = fmaf(v2.y, n2, a.y);
                a.z = fmaf(v2.z, n2, a.z); a.w = fmaf(v2.w, n2, a.w);
                a.x = fmaf(v3.x, n3, a.x); a.y = fmaf(v3.y, n3, a.y);
                a.z = fmaf(v3.z, n3, a.z); a.w = fmaf(v3.w, n3, a.w);
            }
            for (; t < m; t++) {
                int r = __shfl_sync(0xffffffffu, src, t);
                float nn = __shfl_sync(0xffffffffu, nm, t);
                float4 v = __ldg(&g_h[r * 32 + lane]);
                a.x = fmaf(v.x, nn, a.x); a.y = fmaf(v.y, nn, a.y);
                a.z = fmaf(v.z, nn, a.z); a.w = fmaf(v.w, nn, a.w);
            }
        }

        g_acc[w * 32 + lane] = a;

        ps0 += a.x; ps1 += a.y; ps2 += a.z; ps3 += a.w;
        q0 = fmaf(a.x, a.x, q0); q1 = fmaf(a.y, a.y, q1);
        q2 = fmaf(a.z, a.z, q2); q3 = fmaf(a.w, a.w, q3);
    }

    int c = lane * 4;
    atomicAdd(&s_sum[c + 0], ps0);
    atomicAdd(&s_sum[c + 1], ps1);
    atomicAdd(&s_sum[c + 2], ps2);
    atomicAdd(&s_sum[c + 3], ps3);
    atomicAdd(&s_sumsq[c + 0], q0);
    atomicAdd(&s_sumsq[c + 1], q1);
    atomicAdd(&s_sumsq[c + 2], q2);
    atomicAdd(&s_sumsq[c + 3], q3);
    __syncthreads();

    if (tid < DFEAT) {
        atomicAdd(&g_sum[tid], s_sum[tid]);
        atomicAdd(&g_sumsq[tid], s_sumsq[tid]);
    }
}

// -------- 6. BN normalize + relu + residual --------
__global__ void finalize_kernel(const float* __restrict__ x,
                                const float* __restrict__ gamma,
                                const float* __restrict__ beta,
                                float* __restrict__ out, int N) {
    int i = blockIdx.x * blockDim.x + threadIdx.x;
    int total = N * 32;
    if (i >= total) return;
    int d4 = i & 31;
    float inv_n = 1.0f / (float)N;

    float4 a  = g_acc[i];
    float4 xv = ((const float4*)x)[i];
    float4 g  = ((const float4*)gamma)[d4];
    float4 bt = ((const float4*)beta)[d4];
    float4 sm = ((const float4*)g_sum)[d4];
    float4 sq = ((const float4*)g_sumsq)[d4];

    float4 o;
    {
        float m = sm.x * inv_n;
        float var = sq.x * inv_n - m * m;
        float v = (a.x - m) * rsqrtf(var + BN_EPS) * g.x + bt.x;
        o.x = fmaxf(v, 0.f) + xv.x;
    }
    {
        float m = sm.y * inv_n;
        float var = sq.y * inv_n - m * m;
        float v = (a.y - m) * rsqrtf(var + BN_EPS) * g.y + bt.y;
        o.y = fmaxf(v, 0.f) + xv.y;
    }
    {
        float m = sm.z * inv_n;
        float var = sq.z * inv_n - m * m;
        float v = (a.z - m) * rsqrtf(var + BN_EPS) * g.z + bt.z;
        o.z = fmaxf(v, 0.f) + xv.z;
    }
    {
        float m = sm.w * inv_n;
        float var = sq.w * inv_n - m * m;
        float v = (a.w - m) * rsqrtf(var + BN_EPS) * g.w + bt.w;
        o.w = fmaxf(v, 0.f) + xv.w;
    }
    ((float4*)out)[i] = o;
}

extern "C" void kernel_launch(void* const* d_in, const int* in_sizes, int n_in,
                              void* d_out, int out_size) {
    const float* x     = (const float*)d_in[0];
    const int*   ei    = (const int*)d_in[1];
    const float* W     = (const float*)d_in[2];
    const float* b     = (const float*)d_in[3];
    const float* gamma = (const float*)d_in[4];
    const float* beta  = (const float*)d_in[5];
    float*       out   = (float*)d_out;

    int N = in_sizes[0] / DFEAT;
    int E = in_sizes[1] / 2;
    if (E > EMAX) E = EMAX;
    int NB = (N + SCAN_BLK - 1) / SCAN_BLK;   // 196 (<= 256)

    int nstrips = (N + 15) / 16;
    int gemm_blocks = (nstrips + 7) / 8;   // 391
    const int GEMM_SMEM = 65536;

    // one-time resource setup (first call is the uncaptured correctness run;
    // captured calls reuse the same stream/events -> identical graph each time)
    static cudaStream_t s2 = nullptr;
    static cudaEvent_t evFork = nullptr, evJoin = nullptr;
    if (s2 == nullptr) {
        cudaStreamCreateWithFlags(&s2, cudaStreamNonBlocking);
        cudaEventCreateWithFlags(&evFork, cudaEventDisableTiming);
        cudaEventCreateWithFlags(&evJoin, cudaEventDisableTiming);
        cudaFuncSetAttribute(gemm_mma_kernel,
                             cudaFuncAttributeMaxDynamicSharedMemorySize,
                             GEMM_SMEM);
    }

    // prep on main stream (both branches depend on it)
    prep_kernel<<<NB, SCAN_BLK>>>(W, N);

    // fork: chain B (edge preprocessing) on side stream
    cudaEventRecord(evFork, 0);
    cudaStreamWaitEvent(s2, evFork, 0);
    degree_kernel<<<(E + 255) / 256, 256, 0, s2>>>(ei, E, N);
    scan_blocksum_kernel<<<NB, SCAN_BLK, 0, s2>>>(N);
    scan_final_kernel<<<NB, SCAN_BLK, 0, s2>>>(N);
    fill_kernel<<<(E + 255) / 256, 256, 0, s2>>>(ei, E, N);
    cudaEventRecord(evJoin, s2);

    // chain A (gemm) on main stream, concurrent with chain B
    gemm_mma_kernel<<<gemm_blocks, 256, GEMM_SMEM>>>(x, N);

    // join, then gather + finalize
    cudaStreamWaitEvent(0, evJoin, 0);
    gather_kernel<<<GATHER_BLOCKS, 256>>>(b, N);
    finalize_kernel<<<(N * 32 + 255) / 256, 256>>>(x, gamma, beta, out, N);
}

// round 15
// speedup vs baseline: 1.1430x; 1.0526x over previous
#include <cuda_runtime.h>
#include <cuda_bf16.h>
#include <cstdint>

#define DFEAT 128
#define NMAX  50000
#define EMAX  800000
#define BN_EPS 1e-5f
#define SCAN_BLK 256

// -------- scratch (static device globals: no allocation) --------
__device__ float4 g_h[NMAX * 32];           // h = x @ W  (fp32 result)
__device__ float4 g_acc[NMAX * 32];         // gathered output (pre-BN)
__device__ __align__(16) uint2 g_wfh2[4096]; // W hi frags, (bh0,bh1) adjacent
__device__ __align__(16) uint2 g_wfl2[4096]; // W lo frags, (bl0,bl1) adjacent
__device__ float  g_dinv[NMAX];
__device__ __align__(16) int g_ideg[NMAX];
__device__ int    g_indptr[NMAX];
__device__ int    g_cursor[NMAX];
__device__ int    g_srcs[EMAX];
__device__ int    g_bsum[SCAN_BLK];
__device__ __align__(16) float g_sum[DFEAT];
__device__ __align__(16) float g_sumsq[DFEAT];

__device__ __forceinline__ uint32_t pack_bf2(float a, float b) {
    __nv_bfloat16 ha = __float2bfloat16(a);
    __nv_bfloat16 hb = __float2bfloat16(b);
    return (uint32_t)__bfloat16_as_ushort(ha) |
           ((uint32_t)__bfloat16_as_ushort(hb) << 16);
}

// split float2 -> bf16x2 hi + bf16x2 residual
__device__ __forceinline__ void split2(float2 v, uint32_t& hi, uint32_t& lo) {
    __nv_bfloat162 h = __float22bfloat162_rn(v);
    float2 hb = __bfloat1622float2(h);
    hi = *reinterpret_cast<uint32_t*>(&h);
    lo = pack_bf2(v.x - hb.x, v.y - hb.y);
}

// -------- 1. prep: init scratch + pack W fragments (fused) ----------
__global__ void prep_kernel(const float* __restrict__ W, int N) {
    int p = blockIdx.x * blockDim.x + threadIdx.x;

    if (p < N) g_ideg[p] = 0;
    if (p < DFEAT) { g_sum[p] = 0.0f; g_sumsq[p] = 0.0f; }

    if (p >= 4096) return;
    int tig = p & 3;
    int g = (p >> 2) & 7;
    int nt = (p >> 5) & 15;
    int kt = p >> 9;
    int n = nt * 8 + g;
    uint2 wh, wl;
    uint32_t* whp = (uint32_t*)&wh;
    uint32_t* wlp = (uint32_t*)&wl;
#pragma unroll
    for (int half = 0; half < 2; half++) {
        int k = (2 * kt + half) * 8 + tig * 2;
        float w0 = W[k * 128 + n];
        float w1 = W[(k + 1) * 128 + n];
        __nv_bfloat16 h0 = __float2bfloat16(w0);
        __nv_bfloat16 h1 = __float2bfloat16(w1);
        whp[half] = (uint32_t)__bfloat16_as_ushort(h0) |
                    ((uint32_t)__bfloat16_as_ushort(h1) << 16);
        wlp[half] = pack_bf2(w0 - __bfloat162float(h0),
                             w1 - __bfloat162float(h1));
    }
    g_wfh2[p] = wh;
    g_wfl2[p] = wl;
}

// -------- 2A. tensor-core GEMM (stream 0) --------
__device__ __forceinline__ void mma16816(float* d, uint32_t a0, uint32_t a1,
                                         uint32_t a2, uint32_t a3,
                                         uint32_t b0, uint32_t b1) {
    asm volatile(
        "mma.sync.aligned.m16n8k16.row.col.f32.bf16.bf16.f32 "
        "{%0,%1,%2,%3}, {%4,%5,%6,%7}, {%8,%9}, {%0,%1,%2,%3};"
        : "+f"(d[0]), "+f"(d[1]), "+f"(d[2]), "+f"(d[3])
        : "r"(a0), "r"(a1), "r"(a2), "r"(a3), "r"(b0), "r"(b1));
}

__global__ void __launch_bounds__(256) gemm_mma_kernel(
        const float* __restrict__ x, int N) {
    extern __shared__ uint2 s_w2[];
    uint2* s_wh = s_w2;              // 4096 uint2
    uint2* s_wl = s_w2 + 4096;       // 4096 uint2

    {   // stage 64KB of W fragments
        uint4* dh = (uint4*)s_wh;
        uint4* dl = (uint4*)s_wl;
        const uint4* sh = (const uint4*)g_wfh2;
        const uint4* sl = (const uint4*)g_wfl2;
#pragma unroll
        for (int i = threadIdx.x; i < 2048; i += 256) {
            dh[i] = sh[i];
            dl[i] = sl[i];
        }
    }
    __syncthreads();

    int warp = (blockIdx.x * blockDim.x + threadIdx.x) >> 5;
    int lane = threadIdx.x & 31;
    int g = lane >> 2;
    int tig = lane & 3;
    int m0 = warp * 16;
    if (m0 >= N) return;

    int r0i = m0 + g;       if (r0i > N - 1) r0i = N - 1;
    int r1i = m0 + g + 8;   if (r1i > N - 1) r1i = N - 1;

    float d[16][4];
#pragma unroll
    for (int nt = 0; nt < 16; nt++)
#pragma unroll
        for (int c = 0; c < 4; c++) d[nt][c] = 0.f;

    const float2* x2 = (const float2*)x;
    long long rowA = (long long)r0i * 64;
    long long rowA8 = (long long)r1i * 64;

#pragma unroll
    for (int kt = 0; kt < 8; kt++) {
        int kb = kt * 8 + tig;
        uint32_t ah0, ah1, ah2, ah3, al0, al1, al2, al3;
        split2(x2[rowA + kb], ah0, al0);
        split2(x2[rowA8 + kb], ah1, al1);
        split2(x2[rowA + kb + 4], ah2, al2);
        split2(x2[rowA8 + kb + 4], ah3, al3);
#pragma unroll
        for (int nt = 0; nt < 16; nt++) {
            int p = (kt * 16 + nt) * 32 + lane;
            uint2 bh = s_wh[p];
            uint2 bl = s_wl[p];
            mma16816(d[nt], ah0, ah1, ah2, ah3, bh.x, bh.y);
            mma16816(d[nt], ah0, ah1, ah2, ah3, bl.x, bl.y);
            mma16816(d[nt], al0, al1, al2, al3, bh.x, bh.y);
        }
    }

    float* h = (float*)g_h;
    int r0 = m0 + g;
    int r1 = m0 + g + 8;
#pragma unroll
    for (int nt = 0; nt < 16; nt++) {
        int c = nt * 8 + tig * 2;
        if (r0 < N)
            *(float2*)&h[(long long)r0 * 128 + c] = make_float2(d[nt][0], d[nt][1]);
        if (r1 < N)
            *(float2*)&h[(long long)r1 * 128 + c] = make_float2(d[nt][2], d[nt][3]);
    }
}

// -------- 2B. degree (side stream) --------
__global__ void degree_kernel(const int* __restrict__ ei, int E, int N) {
    int e = blockIdx.x * blockDim.x + threadIdx.x;
    if (e < E) {
        int col = ei[E + e];
        if ((unsigned)col < (unsigned)N) atomicAdd(&g_ideg[col], 1);
    }
}

// -------- 3a. per-block degree sums (side stream) --------
__global__ void scan_blocksum_kernel(int N) {
    __shared__ int s[SCAN_BLK];
    int i = blockIdx.x * SCAN_BLK + threadIdx.x;
    s[threadIdx.x] = (i < N) ? g_ideg[i] : 0;
    __syncthreads();
    for (int off = SCAN_BLK / 2; off > 0; off >>= 1) {
        if (threadIdx.x < off) s[threadIdx.x] += s[threadIdx.x + off];
        __syncthreads();
    }
    if (threadIdx.x == 0) g_bsum[blockIdx.x] = s[0];
}

// -------- 3b. scan_final: shuffle-based scan (fewer bar.syncs) ------
__global__ void scan_final_kernel(int N) {
    __shared__ int wsum[8];
    __shared__ int s_off;
    int t = threadIdx.x;
    int lane = t & 31;
    int wid = t >> 5;

    // block offset = sum of g_bsum[0 .. blockIdx.x)  (<= 256 entries)
    int part = 0;
    for (int j = t; j < blockIdx.x; j += SCAN_BLK) part += g_bsum[j];
#pragma unroll
    for (int off = 16; off > 0; off >>= 1)
        part += __shfl_down_sync(0xffffffffu, part, off);
    __shared__ int redw[8];
    if (lane == 0) redw[wid] = part;
    __syncthreads();
    if (t == 0) {
        int acc = 0;
#pragma unroll
        for (int wv = 0; wv < 8; wv++) acc += redw[wv];
        s_off = acc;
    }

    // block-local inclusive scan via warp shuffles
    int i = blockIdx.x * SCAN_BLK + t;
    int v = (i < N) ? g_ideg[i] : 0;
    int sc = v;
#pragma unroll
    for (int off = 1; off < 32; off <<= 1) {
        int nval = __shfl_up_sync(0xffffffffu, sc, off);
        if (lane >= off) sc += nval;
    }
    if (lane == 31) wsum[wid] = sc;
    __syncthreads();
    int wadd = 0;
#pragma unroll
    for (int wv = 0; wv < 8; wv++)
        wadd += (wv < wid) ? wsum[wv] : 0;

    if (i < N) {
        int start = s_off + wadd + sc - v;
        g_indptr[i] = start;
        g_cursor[i] = start;
        g_dinv[i] = rsqrtf((float)(v + 1));
    }
}

// -------- 4. CSR fill (side stream, full-grid parallelism) --------
__global__ void fill_kernel(const int* __restrict__ ei, int E, int N) {
    int e = blockIdx.x * blockDim.x + threadIdx.x;
    if (e < E) {
        int row = ei[e];
        int col = ei[E + e];
        if ((unsigned)row < (unsigned)N && (unsigned)col < (unsigned)N) {
            int pos = atomicAdd(&g_cursor[col], 1);
            if ((unsigned)pos < (unsigned)EMAX) g_srcs[pos] = row;
        }
    }
}

// -------- 5. gather + fused BN stats (unroll-8 for MLP) --------
#define GATHER_BLOCKS 1184
__global__ void __launch_bounds__(256) gather_kernel(
        const float* __restrict__ b, int N) {
    __shared__ float s_sum[DFEAT];
    __shared__ float s_sumsq[DFEAT];
    int tid = threadIdx.x;
    if (tid < DFEAT) { s_sum[tid] = 0.f; s_sumsq[tid] = 0.f; }
    __syncthreads();

    int lane = tid & 31;
    int warp_g = (blockIdx.x * blockDim.x + tid) >> 5;
    int nwarps = (GATHER_BLOCKS * 256) >> 5;

    float4 bb = ((const float4*)b)[lane];

    float ps0 = 0.f, ps1 = 0.f, ps2 = 0.f, ps3 = 0.f;
    float q0 = 0.f, q1 = 0.f, q2 = 0.f, q3 = 0.f;

    for (int w = warp_g; w < N; w += nwarps) {
        float di = g_dinv[w];
        int start = g_indptr[w];
        int cnt = g_ideg[w];

        float4 a = __ldg(&g_h[w * 32 + lane]);
        float selfn = di * di;
        a.x = fmaf(a.x, selfn, bb.x);
        a.y = fmaf(a.y, selfn, bb.y);
        a.z = fmaf(a.z, selfn, bb.z);
        a.w = fmaf(a.w, selfn, bb.w);

        for (int base = 0; base < cnt; base += 32) {
            int j = base + lane;
            int src = 0;
            float nm = 0.f;
            if (j < cnt) {
                src = g_srcs[start + j];
                nm = di * g_dinv[src];
            }
            int m = cnt - base; if (m > 32) m = 32;

            int t = 0;
            for (; t + 8 <= m; t += 8) {
                int r0 = __shfl_sync(0xffffffffu, src, t + 0);
                int r1 = __shfl_sync(0xffffffffu, src, t + 1);
                int r2 = __shfl_sync(0xffffffffu, src, t + 2);
                int r3 = __shfl_sync(0xffffffffu, src, t + 3);
                int r4 = __shfl_sync(0xffffffffu, src, t + 4);
                int r5 = __shfl_sync(0xffffffffu, src, t + 5);
                int r6 = __shfl_sync(0xffffffffu, src, t + 6);
                int r7 = __shfl_sync(0xffffffffu, src, t + 7);
                float n0 = __shfl_sync(0xffffffffu, nm, t + 0);
                float n1 = __shfl_sync(0xffffffffu, nm, t + 1);
                float n2 = __shfl_sync(0xffffffffu, nm, t + 2);
                float n3 = __shfl_sync(0xffffffffu, nm, t + 3);
                float n4 = __shfl_sync(0xffffffffu, nm, t + 4);
                float n5 = __shfl_sync(0xffffffffu, nm, t + 5);
                float n6 = __shfl_sync(0xffffffffu, nm, t + 6);
                float n7 = __shfl_sync(0xffffffffu, nm, t + 7);
                float4 v0 = __ldg(&g_h[r0 * 32 + lane]);
                float4 v1 = __ldg(&g_h[r1 * 32 + lane]);
                float4 v2 = __ldg(&g_h[r2 * 32 + lane]);
                float4 v3 = __ldg(&g_h[r3 * 32 + lane]);
                float4 v4 = __ldg(&g_h[r4 * 32 + lane]);
                float4 v5 = __ldg(&g_h[r5 * 32 + lane]);
                float4 v6 = __ldg(&g_h[r6 * 32 + lane]);
                float4 v7 = __ldg(&g_h[r7 * 32 + lane]);
                a.x = fmaf(v0.x, n0, a.x); a.y = fmaf(v0.y, n0, a.y);
                a.z = fmaf(v0.z, n0, a.z); a.w = fmaf(v0.w, n0, a.w);
                a.x = fmaf(v1.x, n1, a.x); a.y = fmaf(v1.y, n1, a.y);
                a.z = fmaf(v1.z, n1, a.z); a.w = fmaf(v1.w, n1, a.w);
                a.x = fmaf(v2.x, n2, a.x); a.y = fmaf(v2.y, n2, a.y);
                a.z = fmaf(v2.z, n2, a.z); a.w = fmaf(v2.w, n2, a.w);
                a.x = fmaf(v3.x, n3, a.x); a.y = fmaf(v3.y, n3, a.y);
                a.z = fmaf(v3.z, n3, a.z); a.w = fmaf(v3.w, n3, a.w);
                a.x = fmaf(v4.x, n4, a.x); a.y = fmaf(v4.y, n4, a.y);
                a.z = fmaf(v4.z, n4, a.z); a.w = fmaf(v4.w, n4, a.w);
                a.x = fmaf(v5.x, n5, a.x); a.y = fmaf(v5.y, n5, a.y);
                a.z = fmaf(v5.z, n5, a.z); a.w = fmaf(v5.w, n5, a.w);
                a.x = fmaf(v6.x, n6, a.x); a.y = fmaf(v6.y, n6, a.y);
                a.z = fmaf(v6.z, n6, a.z); a.w = fmaf(v6.w, n6, a.w);
                a.x = fmaf(v7.x, n7, a.x); a.y = fmaf(v7.y, n7, a.y);
                a.z = fmaf(v7.z, n7, a.z); a.w = fmaf(v7.w, n7, a.w);
            }
            for (; t + 4 <= m; t += 4) {
                int r0 = __shfl_sync(0xffffffffu, src, t + 0);
                int r1 = __shfl_sync(0xffffffffu, src, t + 1);
                int r2 = __shfl_sync(0xffffffffu, src, t + 2);
                int r3 = __shfl_sync(0xffffffffu, src, t + 3);
                float n0 = __shfl_sync(0xffffffffu, nm, t + 0);
                float n1 = __shfl_sync(0xffffffffu, nm, t + 1);
                float n2 = __shfl_sync(0xffffffffu, nm, t + 2);
                float n3 = __shfl_sync(0xffffffffu, nm, t + 3);
                float4 v0 = __ldg(&g_h[r0 * 32 + lane]);
                float4 v1 = __ldg(&g_h[r1 * 32 + lane]);
                float4 v2 = __ldg(&g_h[r2 * 32 + lane]);
                float4 v3 = __ldg(&g_h[r3 * 32 + lane]);
                a.x = fmaf(v0.x, n0, a.x); a.y = fmaf(v0.y, n0, a.y);
                a.z = fmaf(v0.z, n0, a.z); a.w = fmaf(v0.w, n0, a.w);
                a.x = fmaf(v1.x, n1, a.x); a.y = fmaf(v1.y, n1, a.y);
                a.z = fmaf(v1.z, n1, a.z); a.w = fmaf(v1.w, n1, a.w);
                a.x = fmaf(v2.x, n2, a.x); a.y = fmaf(v2.y, n2, a.y);
                a.z = fmaf(v2.z, n2, a.z); a.w = fmaf(v2.w, n2, a.w);
                a.x = fmaf(v3.x, n3, a.x); a.y = fmaf(v3.y, n3, a.y);
                a.z = fmaf(v3.z, n3, a.z); a.w = fmaf(v3.w, n3, a.w);
            }
            for (; t < m; t++) {
                int r = __shfl_sync(0xffffffffu, src, t);
                float nn = __shfl_sync(0xffffffffu, nm, t);
                float4 v = __ldg(&g_h[r * 32 + lane]);
                a.x = fmaf(v.x, nn, a.x); a.y = fmaf(v.y, nn, a.y);
                a.z = fmaf(v.z, nn, a.z); a.w = fmaf(v.w, nn, a.w);
            }
        }

        g_acc[w * 32 + lane] = a;

        ps0 += a.x; ps1 += a.y; ps2 += a.z; ps3 += a.w;
        q0 = fmaf(a.x, a.x, q0); q1 = fmaf(a.y, a.y, q1);
        q2 = fmaf(a.z, a.z, q2); q3 = fmaf(a.w, a.w, q3);
    }

    int c = lane * 4;
    atomicAdd(&s_sum[c + 0], ps0);
    atomicAdd(&s_sum[c + 1], ps1);
    atomicAdd(&s_sum[c + 2], ps2);
    atomicAdd(&s_sum[c + 3], ps3);
    atomicAdd(&s_sumsq[c + 0], q0);
    atomicAdd(&s_sumsq[c + 1], q1);
    atomicAdd(&s_sumsq[c + 2], q2);
    atomicAdd(&s_sumsq[c + 3], q3);
    __syncthreads();

    if (tid < DFEAT) {
        atomicAdd(&g_sum[tid], s_sum[tid]);
        atomicAdd(&g_sumsq[tid], s_sumsq[tid]);
    }
}

// -------- 6. BN normalize + relu + residual --------
__global__ void finalize_kernel(const float* __restrict__ x,
                                const float* __restrict__ gamma,
                                const float* __restrict__ beta,
                                float* __restrict__ out, int N) {
    int i = blockIdx.x * blockDim.x + threadIdx.x;
    int total = N * 32;
    if (i >= total) return;
    int d4 = i & 31;
    float inv_n = 1.0f / (float)N;

    float4 a  = g_acc[i];
    float4 xv = ((const float4*)x)[i];
    float4 g  = ((const float4*)gamma)[d4];
    float4 bt = ((const float4*)beta)[d4];
    float4 sm = ((const float4*)g_sum)[d4];
    float4 sq = ((const float4*)g_sumsq)[d4];

    float4 o;
    {
        float m = sm.x * inv_n;
        float var = sq.x * inv_n - m * m;
        float v = (a.x - m) * rsqrtf(var + BN_EPS) * g.x + bt.x;
        o.x = fmaxf(v, 0.f) + xv.x;
    }
    {
        float m = sm.y * inv_n;
        float var = sq.y * inv_n - m * m;
        float v = (a.y - m) * rsqrtf(var + BN_EPS) * g.y + bt.y;
        o.y = fmaxf(v, 0.f) + xv.y;
    }
    {
        float m = sm.z * inv_n;
        float var = sq.z * inv_n - m * m;
        float v = (a.z - m) * rsqrtf(var + BN_EPS) * g.z + bt.z;
        o.z = fmaxf(v, 0.f) + xv.z;
    }
    {
        float m = sm.w * inv_n;
        float var = sq.w * inv_n - m * m;
        float v = (a.w - m) * rsqrtf(var + BN_EPS) * g.w + bt.w;
        o.w = fmaxf(v, 0.f) + xv.w;
    }
    ((float4*)out)[i] = o;
}

extern "C" void kernel_launch(void* const* d_in, const int* in_sizes, int n_in,
                              void* d_out, int out_size) {
    const float* x     = (const float*)d_in[0];
    const int*   ei    = (const int*)d_in[1];
    const float* W     = (const float*)d_in[2];
    const float* b     = (const float*)d_in[3];
    const float* gamma = (const float*)d_in[4];
    const float* beta  = (const float*)d_in[5];
    float*       out   = (float*)d_out;

    int N = in_sizes[0] / DFEAT;
    int E = in_sizes[1] / 2;
    if (E > EMAX) E = EMAX;
    int NB = (N + SCAN_BLK - 1) / SCAN_BLK;   // 196 (<= 256)

    int nstrips = (N + 15) / 16;
    int gemm_blocks = (nstrips + 7) / 8;   // 391
    const int GEMM_SMEM = 65536;

    static cudaStream_t s2 = nullptr;
    static cudaEvent_t evFork = nullptr, evJoin = nullptr;
    if (s2 == nullptr) {
        cudaStreamCreateWithFlags(&s2, cudaStreamNonBlocking);
        cudaEventCreateWithFlags(&evFork, cudaEventDisableTiming);
        cudaEventCreateWithFlags(&evJoin, cudaEventDisableTiming);
        cudaFuncSetAttribute(gemm_mma_kernel,
                             cudaFuncAttributeMaxDynamicSharedMemorySize,
                             GEMM_SMEM);
    }

    // prep on main stream (both branches depend on it)
    prep_kernel<<<NB, SCAN_BLK>>>(W, N);

    // fork: chain B (edge preprocessing) on side stream
    cudaEventRecord(evFork, 0);
    cudaStreamWaitEvent(s2, evFork, 0);
    degree_kernel<<<(E + 255) / 256, 256, 0, s2>>>(ei, E, N);
    scan_blocksum_kernel<<<NB, SCAN_BLK, 0, s2>>>(N);
    scan_final_kernel<<<NB, SCAN_BLK, 0, s2>>>(N);
    fill_kernel<<<(E + 255) / 256, 256, 0, s2>>>(ei, E, N);
    cudaEventRecord(evJoin, s2);

    // chain A (gemm) on main stream, concurrent with chain B
    gemm_mma_kernel<<<gemm_blocks, 256, GEMM_SMEM>>>(x, N);

    // join, then gather + finalize
    cudaStreamWaitEvent(0, evJoin, 0);
    gather_kernel<<<GATHER_BLOCKS, 256>>>(b, N);
    finalize_kernel<<<(N * 32 + 255) / 256, 256>>>(x, gamma, beta, out, N);
}